// round 14
// baseline (speedup 1.0000x reference)
#include <cuda_runtime.h>
#include <cstdint>
#include <cstddef>

// LocalConvolution via single-pass TF32 warp MMA (mma.sync m16n8k8).
// R14 = R13 + k-permutation within each 16-k group (g(m)=4(m&3)+(m>>2)) so
// each thread's A values for two k8-steps are 4 consecutive raw W floats ->
// one LDS.128 instead of four LDS.32 (A LDS ops cut 4x; total LDS 128->80
// per warp per tile; smem crossbar was the binder at nw>=4).
// W smem: 256B rows + XOR-64 row-parity swizzle (conflict-free).
// Per CTA (pos): D[o=128, b=64] = W[128,K] @ P[64,K]^T, K = 1600.

#define B_  64
#define C_  64
#define H_  32
#define W_  32
#define CC  28
#define O_  128
#define K_  1600
#define KT  64
#define NTILES 25
#define NPOS 784
#define CHW (C_*H_*W_)        // 65536
#define NTH 256

// per-stage smem:
//  W f32 [128 rows][256B] XOR-64 swizzled by row parity
//  P tf32 [64 k-rows][72 floats = 288B] (global-k order; bank-safe broadcast)
#define WROWB 256
#define PROWB 288
#define WST_OFF 0                     // 128*256 = 32768
#define PTF_OFF 32768                 // 64*288  = 18432
#define STAGESZ (32768 + 18432)       // 51200
#define SMEM_TOTAL (2*STAGESZ)        // 102400

__device__ uint4 g_xtf[CHW * B_ * 4 / 16];   // tf32 (f32-width) [chw][b]

__device__ __forceinline__ uint32_t smem_u32(const void* p) {
    uint32_t a;
    asm("{ .reg .u64 t; cvta.to.shared.u64 t, %1; cvt.u32.u64 %0, t; }" : "=r"(a) : "l"(p));
    return a;
}

__device__ __forceinline__ uint32_t f2tf32(float f) {
    uint32_t r;
    asm("cvt.rna.tf32.f32 %0, %1;" : "=r"(r) : "f"(f));
    return r;
}

__device__ __forceinline__ void cp16(uint32_t smem_dst, const void* gmem_src) {
    asm volatile("cp.async.cg.shared.global [%0], [%1], 16;"
                 :: "r"(smem_dst), "l"(__cvta_generic_to_global(gmem_src)) : "memory");
}

__device__ __forceinline__ float4 lds128f(uint32_t addr) {
    float4 v;
    asm volatile("ld.shared.v4.f32 {%0,%1,%2,%3}, [%4];"
                 : "=f"(v.x), "=f"(v.y), "=f"(v.z), "=f"(v.w) : "r"(addr));
    return v;
}

__device__ __forceinline__ uint32_t lds32u(uint32_t addr) {
    uint32_t v;
    asm volatile("ld.shared.u32 %0, [%1];" : "=r"(v) : "r"(addr));
    return v;
}

__device__ __forceinline__ void mma_tf32(float* d, const uint32_t* a, uint32_t b0, uint32_t b1) {
    asm volatile(
        "mma.sync.aligned.m16n8k8.row.col.f32.tf32.tf32.f32 "
        "{%0,%1,%2,%3}, {%4,%5,%6,%7}, {%8,%9}, {%0,%1,%2,%3};"
        : "+f"(d[0]), "+f"(d[1]), "+f"(d[2]), "+f"(d[3])
        : "r"(a[0]), "r"(a[1]), "r"(a[2]), "r"(a[3]), "r"(b0), "r"(b1));
}

// ---- prep: x[b][chw] f32 -> g_xtf [chw][b] tf32 (rna-rounded) ----
__global__ __launch_bounds__(256)
void prep_kernel(const float* __restrict__ x) {
    __shared__ float ts[B_][65];
    const int tid = threadIdx.x;
    const int wid = tid >> 5;
    const int lane = tid & 31;
    const int chw0 = blockIdx.x * 64;

    #pragma unroll
    for (int bi = 0; bi < 8; bi++) {
        int b = wid * 8 + bi;
        const float* xp = x + (size_t)b * CHW + chw0;
        ts[b][lane]      = xp[lane];
        ts[b][lane + 32] = xp[lane + 32];
    }
    __syncthreads();

    const int chw_l = tid >> 2;
    const int bc = tid & 3;
    uint32_t v[16];
    #pragma unroll
    for (int p = 0; p < 16; p++)
        v[p] = f2tf32(ts[bc * 16 + p][chw_l]);
    char* op = (char*)g_xtf + (size_t)(chw0 + chw_l) * 256 + bc * 64;
    *(uint4*)(op)      = make_uint4(v[0],  v[1],  v[2],  v[3]);
    *(uint4*)(op + 16) = make_uint4(v[4],  v[5],  v[6],  v[7]);
    *(uint4*)(op + 32) = make_uint4(v[8],  v[9],  v[10], v[11]);
    *(uint4*)(op + 48) = make_uint4(v[12], v[13], v[14], v[15]);
}

// ---- main kernel: 256 threads, 8 warps of 32o x 32b ----
__global__ __launch_bounds__(NTH, 2)
void lc_hmma_kernel(const float* __restrict__ x,
                    const float* __restrict__ w,
                    float* __restrict__ out) {
    extern __shared__ char smem[];
    const uint32_t sbase = smem_u32(smem);

    const int tid = threadIdx.x;
    const int wid = tid >> 5;
    const int l   = tid & 31;

    const int pos = blockIdx.x;
    const int i = pos / CC;
    const int j = pos - i * CC;
    const float* __restrict__ wbase = w + (size_t)pos * (O_ * K_);

    const int o0 = (wid >> 1) * 32;
    const int b0 = (wid & 1) * 32;
    const int c4 = l & 3;
    const int r8 = l >> 2;

    // ---- cp.async stage fill for tile t into stage s ----
    auto stage_fill = [&](int t, int s) {
        const uint32_t stOff = sbase + (uint32_t)s * STAGESZ;
        const float* wt = wbase + t * KT;
        // W: 2048 granules of 16B, 8 per thread; XOR-64 swizzle by row parity
        #pragma unroll
        for (int ci = 0; ci < 8; ci++) {
            int idx = tid + ci * NTH;
            int row = idx >> 4;
            int g16 = idx & 15;
            uint32_t dst = (uint32_t)(row * WROWB) + (uint32_t)((g16 * 16) ^ ((row & 1) * 64));
            cp16(stOff + WST_OFF + dst, wt + (size_t)row * K_ + g16 * 4);
        }
        // P: 64 k-rows x 256B = 1024 granules, 4 per thread
        #pragma unroll
        for (int ci = 0; ci < 4; ci++) {
            int idx = tid + ci * NTH;
            int row = idx >> 4;
            int g16 = idx & 15;
            int kg = t * KT + row;
            int c = kg / 25;
            int rem = kg - c * 25;
            int u = rem / 5;
            int v = rem - u * 5;
            size_t sp = ((size_t)(c * (H_ * W_) + (i + u) * W_ + (j + v))) * 256 + g16 * 16;
            cp16(stOff + PTF_OFF + row * PROWB + g16 * 16, (const char*)g_xtf + sp);
        }
        asm volatile("cp.async.commit_group;" ::: "memory");
    };

    // A lane bases (relative): row = o0 + r8 + mi*16 + rh*8, col byte = c4*16
    // full addr = base + (G*64 ^ px), px = (r8&1)*64 (row parity XOR swizzle)
    uint32_t aA[2][2];
    #pragma unroll
    for (int mi = 0; mi < 2; mi++)
        #pragma unroll
        for (int rh = 0; rh < 2; rh++) {
            int row = o0 + r8 + mi * 16 + rh * 8;
            aA[mi][rh] = (uint32_t)(WST_OFF + row * WROWB + c4 * 16);
        }
    const uint32_t px = (uint32_t)((r8 & 1) * 64);
    // B lane base: global k-row = G*16 + 4*c4 + t, n = b0 + bt*8 + r8
    const uint32_t bB = (uint32_t)(PTF_OFF + c4 * 4 * PROWB + (b0 + r8) * 4);

    float acc[2][4][4];
    #pragma unroll
    for (int mi = 0; mi < 2; mi++)
        #pragma unroll
        for (int bt = 0; bt < 4; bt++)
            #pragma unroll
            for (int c = 0; c < 4; c++) acc[mi][bt][c] = 0.0f;

    stage_fill(0, 0);
    stage_fill(1, 1);

    #pragma unroll 1
    for (int t = 0; t < NTILES; t++) {
        if (t == NTILES - 1) {
            asm volatile("cp.async.wait_group 0;" ::: "memory");
        } else {
            asm volatile("cp.async.wait_group 1;" ::: "memory");
        }
        __syncthreads();

        const uint32_t stOff = sbase + (uint32_t)(t & 1) * STAGESZ;

        #pragma unroll
        for (int G = 0; G < 4; G++) {           // four 16-k groups per tile
            // ---- A: 4 x LDS.128 covers BOTH k8-steps of this group ----
            const uint32_t gcol = (uint32_t)(G * 64) ^ px;
            float4 wa[2][2];
            #pragma unroll
            for (int mi = 0; mi < 2; mi++)
                #pragma unroll
                for (int rh = 0; rh < 2; rh++)
                    wa[mi][rh] = lds128f(stOff + aA[mi][rh] + gcol);

            const uint32_t bG = stOff + bB + (uint32_t)(G * 16 * PROWB);

            // ---- step s = 0: MMA cols {c, c+4} -> global {4c, 4c+1} ----
            {
                uint32_t a[2][4];
                #pragma unroll
                for (int mi = 0; mi < 2; mi++) {
                    a[mi][0] = f2tf32(wa[mi][0].x);
                    a[mi][1] = f2tf32(wa[mi][1].x);
                    a[mi][2] = f2tf32(wa[mi][0].y);
                    a[mi][3] = f2tf32(wa[mi][1].y);
                }
                #pragma unroll
                for (int bt = 0; bt < 4; bt++) {
                    uint32_t bb0 = lds32u(bG + bt * 32);
                    uint32_t bb1 = lds32u(bG + PROWB + bt * 32);
                    #pragma unroll
                    for (int mi = 0; mi < 2; mi++)
                        mma_tf32(acc[mi][bt], a[mi], bb0, bb1);
                }
            }
            // ---- step s = 1: MMA cols -> global {4c+2, 4c+3} ----
            {
                uint32_t a[2][4];
                #pragma unroll
                for (int mi = 0; mi < 2; mi++) {
                    a[mi][0] = f2tf32(wa[mi][0].z);
                    a[mi][1] = f2tf32(wa[mi][1].z);
                    a[mi][2] = f2tf32(wa[mi][0].w);
                    a[mi][3] = f2tf32(wa[mi][1].w);
                }
                #pragma unroll
                for (int bt = 0; bt < 4; bt++) {
                    uint32_t bb0 = lds32u(bG + 2 * PROWB + bt * 32);
                    uint32_t bb1 = lds32u(bG + 3 * PROWB + bt * 32);
                    #pragma unroll
                    for (int mi = 0; mi < 2; mi++)
                        mma_tf32(acc[mi][bt], a[mi], bb0, bb1);
                }
            }
        }
        __syncthreads();

        if (t + 2 < NTILES) stage_fill(t + 2, t & 1);
    }

    // ---- epilogue: o = o0+mi*16+(l>>2)+8*(c>>1), b = b0+bt*8+(l&3)*2+(c&1)
    const int orow = r8;
    const int bcol = c4 * 2;
    #pragma unroll
    for (int mi = 0; mi < 2; mi++) {
        #pragma unroll
        for (int bt = 0; bt < 4; bt++) {
            #pragma unroll
            for (int c = 0; c < 4; c++) {
                int o = o0 + mi * 16 + orow + (c >> 1) * 8;
                int b = b0 + bt * 8 + bcol + (c & 1);
                out[((size_t)b * O_ + o) * NPOS + pos] = acc[mi][bt][c];
            }
        }
    }
}

extern "C" void kernel_launch(void* const* d_in, const int* in_sizes, int n_in,
                              void* d_out, int out_size) {
    const float* x;
    const float* w;
    if (in_sizes[0] == B_ * C_ * H_ * W_) {
        x = (const float*)d_in[0];
        w = (const float*)d_in[1];
    } else {
        x = (const float*)d_in[1];
        w = (const float*)d_in[0];
    }
    float* out = (float*)d_out;
    prep_kernel<<<CHW / 64, 256>>>(x);
    cudaFuncSetAttribute(lc_hmma_kernel, cudaFuncAttributeMaxDynamicSharedMemorySize, SMEM_TOTAL);
    lc_hmma_kernel<<<NPOS, NTH, SMEM_TOTAL>>>(x, w, out);
}

// round 15
// speedup vs baseline: 1.2055x; 1.2055x over previous
#include <cuda_runtime.h>
#include <cstdint>
#include <cstddef>

// LocalConvolution via single-pass TF32 warp MMA (mma.sync m16n8k8).
// R15 = R13 fragment math + (1) persistent CTAs with atomic position
// stealing (kills the 2.65-wave tail), (2) 4-stage cp.async ring (KT=32,
// fill t+3, ONE sync per tile; two syncs separate readers from overwrite).
// W streams raw f32; A-frags via conflict-free LDS.32 + cvt.rna.tf32.
// P pre-converted to tf32 [chw][b] by prep. Per position:
// D[o=128, b=64] = W[128,K] @ P[64,K]^T, K = 1600.

#define B_  64
#define C_  64
#define H_  32
#define W_  32
#define CC  28
#define O_  128
#define K_  1600
#define KT  32
#define NTILES 50
#define NPOS 784
#define CHW (C_*H_*W_)        // 65536
#define NTH 256
#define GRID 304

// per-stage smem:
//  W f32 [128 rows][36 floats = 144B]  (bank (36r+c)%32: conflict-free phases)
//  P tf32 [32 k-rows][72 floats = 288B]
#define WROWB 144
#define PROWB 288
#define WST_OFF 0                     // 128*144 = 18432
#define PTF_OFF 18432                 // 32*288  = 9216
#define STAGESZ (18432 + 9216)        // 27648
#define SMEM_TOTAL (4*STAGESZ)        // 110592

__device__ uint4 g_xtf[CHW * B_ * 4 / 16];   // tf32 (f32-width) [chw][b]
__device__ int   g_pos_ctr;

__device__ __forceinline__ uint32_t smem_u32(const void* p) {
    uint32_t a;
    asm("{ .reg .u64 t; cvta.to.shared.u64 t, %1; cvt.u32.u64 %0, t; }" : "=r"(a) : "l"(p));
    return a;
}

__device__ __forceinline__ uint32_t f2tf32(float f) {
    uint32_t r;
    asm("cvt.rna.tf32.f32 %0, %1;" : "=r"(r) : "f"(f));
    return r;
}

__device__ __forceinline__ void cp16(uint32_t smem_dst, const void* gmem_src) {
    asm volatile("cp.async.cg.shared.global [%0], [%1], 16;"
                 :: "r"(smem_dst), "l"(__cvta_generic_to_global(gmem_src)) : "memory");
}

__device__ __forceinline__ float lds32f(uint32_t addr) {
    float v;
    asm volatile("ld.shared.f32 %0, [%1];" : "=f"(v) : "r"(addr));
    return v;
}

__device__ __forceinline__ uint32_t lds32u(uint32_t addr) {
    uint32_t v;
    asm volatile("ld.shared.u32 %0, [%1];" : "=r"(v) : "r"(addr));
    return v;
}

__device__ __forceinline__ void mma_tf32(float* d, const uint32_t* a, uint32_t b0, uint32_t b1) {
    asm volatile(
        "mma.sync.aligned.m16n8k8.row.col.f32.tf32.tf32.f32 "
        "{%0,%1,%2,%3}, {%4,%5,%6,%7}, {%8,%9}, {%0,%1,%2,%3};"
        : "+f"(d[0]), "+f"(d[1]), "+f"(d[2]), "+f"(d[3])
        : "r"(a[0]), "r"(a[1]), "r"(a[2]), "r"(a[3]), "r"(b0), "r"(b1));
}

// ---- prep: x[b][chw] f32 -> g_xtf [chw][b] tf32; resets the work counter ----
__global__ __launch_bounds__(256)
void prep_kernel(const float* __restrict__ x) {
    __shared__ float ts[B_][65];
    const int tid = threadIdx.x;
    const int wid = tid >> 5;
    const int lane = tid & 31;
    const int chw0 = blockIdx.x * 64;

    if (blockIdx.x == 0 && tid == 0) g_pos_ctr = 0;

    #pragma unroll
    for (int bi = 0; bi < 8; bi++) {
        int b = wid * 8 + bi;
        const float* xp = x + (size_t)b * CHW + chw0;
        ts[b][lane]      = xp[lane];
        ts[b][lane + 32] = xp[lane + 32];
    }
    __syncthreads();

    const int chw_l = tid >> 2;
    const int bc = tid & 3;
    uint32_t v[16];
    #pragma unroll
    for (int p = 0; p < 16; p++)
        v[p] = f2tf32(ts[bc * 16 + p][chw_l]);
    char* op = (char*)g_xtf + (size_t)(chw0 + chw_l) * 256 + bc * 64;
    *(uint4*)(op)      = make_uint4(v[0],  v[1],  v[2],  v[3]);
    *(uint4*)(op + 16) = make_uint4(v[4],  v[5],  v[6],  v[7]);
    *(uint4*)(op + 32) = make_uint4(v[8],  v[9],  v[10], v[11]);
    *(uint4*)(op + 48) = make_uint4(v[12], v[13], v[14], v[15]);
}

// ---- main kernel: persistent, 256 threads, 8 warps of 32o x 32b ----
__global__ __launch_bounds__(NTH, 2)
void lc_hmma_kernel(const float* __restrict__ x,
                    const float* __restrict__ w,
                    float* __restrict__ out) {
    extern __shared__ char smem[];
    const uint32_t sbase = smem_u32(smem);

    const int tid = threadIdx.x;
    const int wid = tid >> 5;
    const int l   = tid & 31;

    const int o0 = (wid >> 1) * 32;
    const int b0 = (wid & 1) * 32;
    const int c4 = l & 3;
    const int r8 = l >> 2;

    // shared slot for the stolen position index
    __shared__ int s_pos;

    // A lane bases (relative to stage): rows o0+r8+{0,8,16,24}, col byte c4*4
    uint32_t aA[2][2];
    #pragma unroll
    for (int mi = 0; mi < 2; mi++)
        #pragma unroll
        for (int rh = 0; rh < 2; rh++)
            aA[mi][rh] = (uint32_t)(WST_OFF + (o0 + r8 + mi * 16 + rh * 8) * WROWB + c4 * 4);
    // B lane base: k-row = c4, n = b0 + r8
    const uint32_t bB = (uint32_t)(PTF_OFF + c4 * PROWB + (b0 + r8) * 4);

    while (true) {
        if (tid == 0) s_pos = atomicAdd(&g_pos_ctr, 1);
        __syncthreads();
        const int pos = s_pos;
        if (pos >= NPOS) break;

        const int i = pos / CC;
        const int j = pos - i * CC;
        const float* __restrict__ wbase = w + (size_t)pos * (O_ * K_);

        // ---- stage fill for tile t into stage t&3 ----
        auto stage_fill = [&](int t) {
            const uint32_t stOff = sbase + (uint32_t)(t & 3) * STAGESZ;
            const float* wt = wbase + t * KT;
            // W: 128 rows x 32 f32 = 1024 granules of 16B, 4 per thread
            #pragma unroll
            for (int ci = 0; ci < 4; ci++) {
                int idx = tid + ci * NTH;
                int row = idx >> 3;
                int g8 = idx & 7;
                cp16(stOff + WST_OFF + row * WROWB + g8 * 16,
                     wt + (size_t)row * K_ + g8 * 4);
            }
            // P: 32 k-rows x 256B = 512 granules, 2 per thread
            #pragma unroll
            for (int ci = 0; ci < 2; ci++) {
                int idx = tid + ci * NTH;
                int row = idx >> 4;
                int g16 = idx & 15;
                int kg = t * KT + row;
                int c = kg / 25;
                int rem = kg - c * 25;
                int u = rem / 5;
                int v = rem - u * 5;
                size_t sp = ((size_t)(c * (H_ * W_) + (i + u) * W_ + (j + v))) * 256 + g16 * 16;
                cp16(stOff + PTF_OFF + row * PROWB + g16 * 16, (const char*)g_xtf + sp);
            }
            asm volatile("cp.async.commit_group;" ::: "memory");
        };

        float acc[2][4][4];
        #pragma unroll
        for (int mi = 0; mi < 2; mi++)
            #pragma unroll
            for (int bt = 0; bt < 4; bt++)
                #pragma unroll
                for (int c = 0; c < 4; c++) acc[mi][bt][c] = 0.0f;

        // prologue: 3 tiles in flight
        stage_fill(0);
        stage_fill(1);
        stage_fill(2);

        #pragma unroll 1
        for (int t = 0; t < NTILES; t++) {
            asm volatile("cp.async.wait_group 2;" ::: "memory");
            __syncthreads();

            const uint32_t stOff = sbase + (uint32_t)(t & 3) * STAGESZ;
            const uint32_t bRow  = stOff + bB;

            #pragma unroll
            for (int ks = 0; ks < 4; ks++) {
                // ---- A fragments: 8 LDS.32 + cvt ----
                const uint32_t aCol = (uint32_t)(ks * 32);
                uint32_t a[2][4];
                #pragma unroll
                for (int mi = 0; mi < 2; mi++) {
                    const uint32_t rb0 = stOff + aA[mi][0] + aCol;
                    const uint32_t rb1 = stOff + aA[mi][1] + aCol;
                    a[mi][0] = f2tf32(lds32f(rb0));
                    a[mi][1] = f2tf32(lds32f(rb1));
                    a[mi][2] = f2tf32(lds32f(rb0 + 16));
                    a[mi][3] = f2tf32(lds32f(rb1 + 16));
                }
                // ---- B fragments: 8 LDS.32 ----
                const uint32_t bk = bRow + (uint32_t)(ks * 8) * PROWB;
                uint32_t b[4][2];
                #pragma unroll
                for (int bt = 0; bt < 4; bt++) {
                    b[bt][0] = lds32u(bk + bt * 32);
                    b[bt][1] = lds32u(bk + 4 * PROWB + bt * 32);
                }
                // ---- 8 MMAs, all-distinct accumulators ----
                #pragma unroll
                for (int mi = 0; mi < 2; mi++)
                    #pragma unroll
                    for (int bt = 0; bt < 4; bt++)
                        mma_tf32(acc[mi][bt], a[mi], b[bt][0], b[bt][1]);
            }

            // fill t+3 (stage (t+3)&3 = (t-1)&3: last read two syncs ago)
            if (t + 3 < NTILES) stage_fill(t + 3);
            else asm volatile("cp.async.commit_group;" ::: "memory");
        }

        // ---- epilogue: o = o0+mi*16+r8+8*(c>>1), b = b0+bt*8+c4*2+(c&1)
        #pragma unroll
        for (int mi = 0; mi < 2; mi++) {
            #pragma unroll
            for (int bt = 0; bt < 4; bt++) {
                #pragma unroll
                for (int c = 0; c < 4; c++) {
                    int o = o0 + mi * 16 + r8 + (c >> 1) * 8;
                    int b = b0 + bt * 8 + c4 * 2 + (c & 1);
                    out[((size_t)b * O_ + o) * NPOS + pos] = acc[mi][bt][c];
                }
            }
        }
        // no warp may start refilling stages for the next position while
        // another warp still reads the last tiles of this one
        __syncthreads();
    }
}

extern "C" void kernel_launch(void* const* d_in, const int* in_sizes, int n_in,
                              void* d_out, int out_size) {
    const float* x;
    const float* w;
    if (in_sizes[0] == B_ * C_ * H_ * W_) {
        x = (const float*)d_in[0];
        w = (const float*)d_in[1];
    } else {
        x = (const float*)d_in[1];
        w = (const float*)d_in[0];
    }
    float* out = (float*)d_out;
    prep_kernel<<<CHW / 64, 256>>>(x);
    cudaFuncSetAttribute(lc_hmma_kernel, cudaFuncAttributeMaxDynamicSharedMemorySize, SMEM_TOTAL);
    lc_hmma_kernel<<<GRID, NTH, SMEM_TOTAL>>>(x, w, out);
}

// round 16
// speedup vs baseline: 1.3164x; 1.0921x over previous
#include <cuda_runtime.h>
#include <cstdint>
#include <cstddef>

// LocalConvolution via single-pass TF32 warp MMA (mma.sync m16n8k8).
// R16 = R13 chassis (2-stage cp.async, KT=64, 784 CTAs, 8 warps of 32o x 32b)
// + explicit double-buffered FRAGMENT prefetch across k8-steps (hides LDS
// latency inside the warp) + A fed as RAW f32 bits (tf32 HW truncation, no
// cvt: frees the registers the prefetch needs). P pre-converted RNA by prep.
// Per CTA (pos): D[o=128, b=64] = W[128,K] @ P[64,K]^T, K = 1600.

#define B_  64
#define C_  64
#define H_  32
#define W_  32
#define CC  28
#define O_  128
#define K_  1600
#define KT  64
#define NTILES 25
#define NPOS 784
#define CHW (C_*H_*W_)        // 65536
#define NTH 256

// per-stage smem:
//  W f32 [128 rows][68 floats = 272B]  (bank = (68r/..)%32: conflict-free)
//  P tf32 [64 k-rows][72 floats = 288B]
#define WROWB 272
#define PROWB 288
#define WST_OFF 0                     // 128*272 = 34816
#define PTF_OFF 34816                 // 64*288  = 18432
#define STAGESZ (34816 + 18432)       // 53248
#define SMEM_TOTAL (2*STAGESZ)        // 106496

__device__ uint4 g_xtf[CHW * B_ * 4 / 16];   // tf32 (f32-width) [chw][b]

__device__ __forceinline__ uint32_t smem_u32(const void* p) {
    uint32_t a;
    asm("{ .reg .u64 t; cvta.to.shared.u64 t, %1; cvt.u32.u64 %0, t; }" : "=r"(a) : "l"(p));
    return a;
}

__device__ __forceinline__ uint32_t f2tf32(float f) {
    uint32_t r;
    asm("cvt.rna.tf32.f32 %0, %1;" : "=r"(r) : "f"(f));
    return r;
}

__device__ __forceinline__ void cp16(uint32_t smem_dst, const void* gmem_src) {
    asm volatile("cp.async.cg.shared.global [%0], [%1], 16;"
                 :: "r"(smem_dst), "l"(__cvta_generic_to_global(gmem_src)) : "memory");
}

__device__ __forceinline__ uint32_t lds32u(uint32_t addr) {
    uint32_t v;
    asm volatile("ld.shared.u32 %0, [%1];" : "=r"(v) : "r"(addr));
    return v;
}

__device__ __forceinline__ void mma_tf32(float* d, const uint32_t* a, uint32_t b0, uint32_t b1) {
    asm volatile(
        "mma.sync.aligned.m16n8k8.row.col.f32.tf32.tf32.f32 "
        "{%0,%1,%2,%3}, {%4,%5,%6,%7}, {%8,%9}, {%0,%1,%2,%3};"
        : "+f"(d[0]), "+f"(d[1]), "+f"(d[2]), "+f"(d[3])
        : "r"(a[0]), "r"(a[1]), "r"(a[2]), "r"(a[3]), "r"(b0), "r"(b1));
}

// ---- prep: x[b][chw] f32 -> g_xtf [chw][b] tf32 (rna-rounded) ----
__global__ __launch_bounds__(256)
void prep_kernel(const float* __restrict__ x) {
    __shared__ float ts[B_][65];
    const int tid = threadIdx.x;
    const int wid = tid >> 5;
    const int lane = tid & 31;
    const int chw0 = blockIdx.x * 64;

    #pragma unroll
    for (int bi = 0; bi < 8; bi++) {
        int b = wid * 8 + bi;
        const float* xp = x + (size_t)b * CHW + chw0;
        ts[b][lane]      = xp[lane];
        ts[b][lane + 32] = xp[lane + 32];
    }
    __syncthreads();

    const int chw_l = tid >> 2;
    const int bc = tid & 3;
    uint32_t v[16];
    #pragma unroll
    for (int p = 0; p < 16; p++)
        v[p] = f2tf32(ts[bc * 16 + p][chw_l]);
    char* op = (char*)g_xtf + (size_t)(chw0 + chw_l) * 256 + bc * 64;
    *(uint4*)(op)      = make_uint4(v[0],  v[1],  v[2],  v[3]);
    *(uint4*)(op + 16) = make_uint4(v[4],  v[5],  v[6],  v[7]);
    *(uint4*)(op + 32) = make_uint4(v[8],  v[9],  v[10], v[11]);
    *(uint4*)(op + 48) = make_uint4(v[12], v[13], v[14], v[15]);
}

// ---- main kernel: 256 threads, 8 warps of 32o x 32b ----
__global__ __launch_bounds__(NTH, 2)
void lc_hmma_kernel(const float* __restrict__ x,
                    const float* __restrict__ w,
                    float* __restrict__ out) {
    extern __shared__ char smem[];
    const uint32_t sbase = smem_u32(smem);

    const int tid = threadIdx.x;
    const int wid = tid >> 5;
    const int l   = tid & 31;

    const int pos = blockIdx.x;
    const int i = pos / CC;
    const int j = pos - i * CC;
    const float* __restrict__ wbase = w + (size_t)pos * (O_ * K_);

    const int o0 = (wid >> 1) * 32;
    const int b0 = (wid & 1) * 32;
    const int c4 = l & 3;
    const int r8 = l >> 2;

    // ---- cp.async stage fill for tile t into stage s ----
    auto stage_fill = [&](int t, int s) {
        const uint32_t stOff = sbase + (uint32_t)s * STAGESZ;
        const float* wt = wbase + t * KT;
        // W: 128 rows x 64 f32 = 2048 granules, 8 per thread
        #pragma unroll
        for (int ci = 0; ci < 8; ci++) {
            int idx = tid + ci * NTH;
            int row = idx >> 4;
            int g16 = idx & 15;
            cp16(stOff + WST_OFF + row * WROWB + g16 * 16,
                 wt + (size_t)row * K_ + g16 * 4);
        }
        // P: 64 k-rows x 256B = 1024 granules, 4 per thread
        #pragma unroll
        for (int ci = 0; ci < 4; ci++) {
            int idx = tid + ci * NTH;
            int row = idx >> 4;
            int g16 = idx & 15;
            int kg = t * KT + row;
            int c = kg / 25;
            int rem = kg - c * 25;
            int u = rem / 5;
            int v = rem - u * 5;
            size_t sp = ((size_t)(c * (H_ * W_) + (i + u) * W_ + (j + v))) * 256 + g16 * 16;
            cp16(stOff + PTF_OFF + row * PROWB + g16 * 16, (const char*)g_xtf + sp);
        }
        asm volatile("cp.async.commit_group;" ::: "memory");
    };

    // A lane base (relative): row = o0 + r8, col(float) = c4
    const uint32_t aBaseRel = (uint32_t)(WST_OFF + (o0 + r8) * WROWB + c4 * 4);
    // B lane base (relative): k-row = c4, n = b0 + r8
    const uint32_t bBaseRel = (uint32_t)(PTF_OFF + c4 * PROWB + (b0 + r8) * 4);

    float acc[2][4][4];
    #pragma unroll
    for (int mi = 0; mi < 2; mi++)
        #pragma unroll
        for (int bt = 0; bt < 4; bt++)
            #pragma unroll
            for (int c = 0; c < 4; c++) acc[mi][bt][c] = 0.0f;

    stage_fill(0, 0);
    stage_fill(1, 1);

    #pragma unroll 1
    for (int t = 0; t < NTILES; t++) {
        if (t == NTILES - 1) {
            asm volatile("cp.async.wait_group 0;" ::: "memory");
        } else {
            asm volatile("cp.async.wait_group 1;" ::: "memory");
        }
        __syncthreads();

        const uint32_t stOff = sbase + (uint32_t)(t & 1) * STAGESZ;
        const uint32_t aBase = stOff + aBaseRel;
        const uint32_t bBase = stOff + bBaseRel;

        // fragment loader for k8-step ks (A raw f32 bits; B pre-tf32)
        auto load_frags = [&](int ks, uint32_t a[2][4], uint32_t b[4][2]) {
            const uint32_t aCol = (uint32_t)(ks * 32);
            #pragma unroll
            for (int mi = 0; mi < 2; mi++) {
                const uint32_t rb0 = aBase + (uint32_t)(mi * 16) * WROWB + aCol;
                const uint32_t rb1 = rb0 + 8 * WROWB;
                a[mi][0] = lds32u(rb0);
                a[mi][1] = lds32u(rb1);
                a[mi][2] = lds32u(rb0 + 16);
                a[mi][3] = lds32u(rb1 + 16);
            }
            const uint32_t bk = bBase + (uint32_t)(ks * 8) * PROWB;
            #pragma unroll
            for (int bt = 0; bt < 4; bt++) {
                b[bt][0] = lds32u(bk + bt * 32);
                b[bt][1] = lds32u(bk + 4 * PROWB + bt * 32);
            }
        };

        uint32_t afr[2][2][4], bfr[2][4][2];
        load_frags(0, afr[0], bfr[0]);
        #pragma unroll
        for (int ks = 0; ks < 8; ks++) {
            const int cur = ks & 1;
            if (ks < 7) load_frags(ks + 1, afr[cur ^ 1], bfr[cur ^ 1]);
            #pragma unroll
            for (int mi = 0; mi < 2; mi++)
                #pragma unroll
                for (int bt = 0; bt < 4; bt++)
                    mma_tf32(acc[mi][bt], afr[cur][mi], bfr[cur][bt][0], bfr[cur][bt][1]);
        }
        __syncthreads();

        if (t + 2 < NTILES) stage_fill(t + 2, t & 1);
    }

    // ---- epilogue: o = o0+mi*16+r8+8*(c>>1), b = b0+bt*8+c4*2+(c&1)
    #pragma unroll
    for (int mi = 0; mi < 2; mi++) {
        #pragma unroll
        for (int bt = 0; bt < 4; bt++) {
            #pragma unroll
            for (int c = 0; c < 4; c++) {
                int o = o0 + mi * 16 + r8 + (c >> 1) * 8;
                int b = b0 + bt * 8 + c4 * 2 + (c & 1);
                out[((size_t)b * O_ + o) * NPOS + pos] = acc[mi][bt][c];
            }
        }
    }
}

extern "C" void kernel_launch(void* const* d_in, const int* in_sizes, int n_in,
                              void* d_out, int out_size) {
    const float* x;
    const float* w;
    if (in_sizes[0] == B_ * C_ * H_ * W_) {
        x = (const float*)d_in[0];
        w = (const float*)d_in[1];
    } else {
        x = (const float*)d_in[1];
        w = (const float*)d_in[0];
    }
    float* out = (float*)d_out;
    prep_kernel<<<CHW / 64, 256>>>(x);
    cudaFuncSetAttribute(lc_hmma_kernel, cudaFuncAttributeMaxDynamicSharedMemorySize, SMEM_TOTAL);
    lc_hmma_kernel<<<NPOS, NTH, SMEM_TOTAL>>>(x, w, out);
}